// round 6
// baseline (speedup 1.0000x reference)
#include <cuda_runtime.h>

#define N_USERS 50000
#define N_ITEMS 75000
#define N_NODES 125000
#define NNZ     1250000
#define EMB     64
#define N_LAYERS 3
#define BATCH   4096
#define SCAN_BLOCKS 489        // ceil(125000/256)

// Scratch (device globals — allocation-free per harness rules)
__device__ __align__(128) float g_feat[N_NODES * EMB];                 // 32 MB
__device__ __align__(128) float g_agg [N_NODES * EMB];                 // 32 MB
__device__ __align__(128) float g_norm[N_LAYERS * N_NODES * EMB];      // 96 MB
// CSR scratch.  INVARIANT: g_cnt is all-zero at kernel_launch entry
// (zero-initialized at load; re-zeroed by gather_kernel every execution).
__device__ __align__(128) int   g_cnt   [N_NODES];
__device__ __align__(128) int   g_rowptr[N_NODES + 1];
__device__ __align__(128) int   g_cursor[N_NODES];
__device__ __align__(128) int   g_bsum  [512];
__device__ __align__(128) int   g_boff  [512];
__device__ __align__(128) int   g_cols  [NNZ];
__device__ __align__(128) float g_vals  [NNZ];

__device__ __forceinline__ float lrelu(float x) {
    return x > 0.0f ? x : 0.2f * x;
}

// Packed fp32x2 FMA (sm_103a FFMA2)
#define FMA2(acc, a, b) \
    asm("fma.rn.f32x2 %0, %1, %2, %0;" : "+l"(acc) : "l"(a), "l"(b))

__device__ __forceinline__ float lo2(unsigned long long v) {
    return __uint_as_float((unsigned)v);
}
__device__ __forceinline__ float hi2(unsigned long long v) {
    return __uint_as_float((unsigned)(v >> 32));
}

// ---------------------------------------------------------------------------
// copy emb -> g_feat, AND histogram rows (g_cnt zero on entry, see invariant)
__global__ __launch_bounds__(256) void copy_hist_kernel(const float* __restrict__ emb,
                                                        const int*   __restrict__ row) {
    int i = blockIdx.x * 256 + threadIdx.x;
    if (i < N_NODES * EMB / 4)
        ((float4*)g_feat)[i] = ((const float4*)emb)[i];
    if (i < NNZ)
        atomicAdd(&g_cnt[row[i]], 1);
}

// ---------------------------------------------------------------------------
// per-block exclusive scan of g_cnt; raw exclusive -> g_rowptr, totals -> g_bsum
__global__ __launch_bounds__(256) void scan1_kernel() {
    __shared__ int s[256];
    int tid = threadIdx.x;
    int i   = blockIdx.x * 256 + tid;
    int x   = (i < N_NODES) ? g_cnt[i] : 0;
    s[tid] = x;
    __syncthreads();
    #pragma unroll
    for (int off = 1; off < 256; off <<= 1) {
        int v = (tid >= off) ? s[tid - off] : 0;
        __syncthreads();
        s[tid] += v;
        __syncthreads();
    }
    if (i < N_NODES) g_rowptr[i] = s[tid] - x;     // exclusive within block
    if (tid == 255) g_bsum[blockIdx.x] = s[255];
}

// single block: exclusive scan of 489 block sums (shfl-based)
__global__ __launch_bounds__(512) void scan2_kernel() {
    __shared__ int wt[16];
    int tid  = threadIdx.x;
    int lane = tid & 31;
    int w    = tid >> 5;
    int x = (tid < SCAN_BLOCKS) ? g_bsum[tid] : 0;
    int v = x;
    #pragma unroll
    for (int off = 1; off < 32; off <<= 1) {
        int n = __shfl_up_sync(0xffffffffu, v, off);
        if (lane >= off) v += n;
    }
    if (lane == 31) wt[w] = v;
    __syncthreads();
    if (w == 0 && lane < 16) {
        int s = wt[lane];
        #pragma unroll
        for (int off = 1; off < 16; off <<= 1) {
            int n = __shfl_up_sync(0x0000ffffu, s, off);
            if (lane >= off) s += n;
        }
        wt[lane] = s;
    }
    __syncthreads();
    int add = (w > 0) ? wt[w - 1] : 0;
    g_boff[tid] = v - x + add;
}

// apply block offsets; init cursor; set sentinel
__global__ __launch_bounds__(256) void scan3_kernel() {
    int i = blockIdx.x * 256 + threadIdx.x;
    if (i < N_NODES) {
        int v = g_rowptr[i] + g_boff[blockIdx.x];
        g_rowptr[i] = v;
        g_cursor[i] = v;
    }
    if (i == 0) g_rowptr[N_NODES] = NNZ;
}

// scatter edges into row-sorted order
__global__ __launch_bounds__(256) void scatter_kernel(const int*   __restrict__ row,
                                                      const int*   __restrict__ col,
                                                      const float* __restrict__ vals) {
    int e = blockIdx.x * 256 + threadIdx.x;
    if (e >= NNZ) return;
    int pos = atomicAdd(&g_cursor[row[e]], 1);
    g_cols[pos] = col[e];
    g_vals[pos] = vals[e];
}

// ---------------------------------------------------------------------------
// Gather-SpMM over CSR: agg[r] = sum_j val[j] * feat[col[j]]
__global__ __launch_bounds__(256) void spmm_csr_kernel() {
    int t   = blockIdx.x * 256 + threadIdx.x;
    int r   = t >> 4;
    int seg = t & 15;
    if (r >= N_NODES) return;
    int j  = g_rowptr[r];
    int s1 = g_rowptr[r + 1];
    float4 acc = make_float4(0.f, 0.f, 0.f, 0.f);
    const float4* feat4 = (const float4*)g_feat;
    for (; j + 1 < s1; j += 2) {
        int   c0 = __ldg(g_cols + j);
        float v0 = __ldg(g_vals + j);
        int   c1 = __ldg(g_cols + j + 1);
        float v1 = __ldg(g_vals + j + 1);
        float4 f0 = __ldg(feat4 + c0 * 16 + seg);
        float4 f1 = __ldg(feat4 + c1 * 16 + seg);
        acc.x += v0 * f0.x + v1 * f1.x;
        acc.y += v0 * f0.y + v1 * f1.y;
        acc.z += v0 * f0.z + v1 * f1.z;
        acc.w += v0 * f0.w + v1 * f1.w;
    }
    if (j < s1) {
        int   c0 = __ldg(g_cols + j);
        float v0 = __ldg(g_vals + j);
        float4 f0 = __ldg(feat4 + c0 * 16 + seg);
        acc.x += v0 * f0.x;
        acc.y += v0 * f0.y;
        acc.z += v0 * f0.z;
        acc.w += v0 * f0.w;
    }
    ((float4*)g_agg)[r * 16 + seg] = acc;
}

// ---------------------------------------------------------------------------
// Dense per-node update. The TWO GEMMs ride in the two halves of f32x2:
//   operand A = (agg, agg*feat) interleaved, operand B = (w1, w2) interleaved,
//   so acc.lo accumulates W1@agg and acc.hi accumulates W2@(agg*feat).
// Block = 256 threads, tile = 128 nodes x 64 outputs; one tile per block.
//   tx = t&15 -> 4 output dims (j0 = tx*4);  ty = t>>4 -> 8 nodes (m0 = ty*8)
#define M_TILE    128
#define AB_STRIDE 264          // 128 nodes * 2 + 8 pad (floats per k-row)
#define WW_STRIDE 132          // 64 j * 2 + 4 pad
#define SAB_FLOATS (64 * AB_STRIDE)                   // 16896
#define SW_FLOATS  (64 * WW_STRIDE)                   // 8448
#define DENSE_SMEM ((SAB_FLOATS + SW_FLOATS) * 4)     // 101376 B

__global__ __launch_bounds__(256, 2) void dense_kernel(const float* __restrict__ W1,
                                                       const float* __restrict__ b1,
                                                       const float* __restrict__ W2,
                                                       const float* __restrict__ b2,
                                                       int layer) {
    extern __shared__ float smem[];
    float* sAB = smem;                       // [64 k][128 m][2]  (a, a*f)
    float* sW  = sAB + SAB_FLOATS;           // [64 k][64 j][2]   (w1, w2)

    const int t    = threadIdx.x;
    const int tx   = t & 15;
    const int ty   = t >> 4;
    const int j0   = tx * 4;
    const int m0   = ty * 8;
    const int base = blockIdx.x * M_TILE;

    // Stage weights interleaved (w1,w2), transposed [k][j] ------------------
    const float* W1l = W1 + layer * 4096;
    const float* W2l = W2 + layer * 4096;
    #pragma unroll
    for (int i = t; i < 4096; i += 256) {
        int j = i >> 6, k = i & 63;
        *(float2*)(sW + k * WW_STRIDE + j * 2) = make_float2(W1l[i], W2l[i]);
    }

    // Stage A interleaved (a, a*f), k-major ---------------------------------
    #pragma unroll
    for (int idx = t; idx < M_TILE * 16; idx += 256) {
        int mm = idx & 127;
        int sg = idx >> 7;                  // 0..15
        int node = base + mm;
        float4 a4 = make_float4(0.f, 0.f, 0.f, 0.f);
        float4 f4 = make_float4(0.f, 0.f, 0.f, 0.f);
        if (node < N_NODES) {
            a4 = ((const float4*)g_agg )[node * 16 + sg];
            f4 = ((const float4*)g_feat)[node * 16 + sg];
        }
        #pragma unroll
        for (int i = 0; i < 4; ++i) {
            float av = (&a4.x)[i];
            float fv = (&f4.x)[i];
            *(float2*)(sAB + (sg * 4 + i) * AB_STRIDE + mm * 2)
                = make_float2(av, av * fv);
        }
    }
    __syncthreads();

    // Main loop: 32 FFMA2 + 6 LDS.128 per k ---------------------------------
    unsigned long long acc[32];             // [m*4 + j], m=0..7 local nodes
    #pragma unroll
    for (int i = 0; i < 32; ++i) acc[i] = 0ull;

    #pragma unroll 4
    for (int k = 0; k < 64; ++k) {
        const ulonglong2* rA = (const ulonglong2*)(sAB + k * AB_STRIDE + m0 * 2);
        const ulonglong2* rW = (const ulonglong2*)(sW  + k * WW_STRIDE + j0 * 2);
        ulonglong2 A01 = rA[0];
        ulonglong2 A23 = rA[1];
        ulonglong2 A45 = rA[2];
        ulonglong2 A67 = rA[3];
        ulonglong2 W01 = rW[0];
        ulonglong2 W23 = rW[1];
        unsigned long long Am[8] = {A01.x, A01.y, A23.x, A23.y,
                                    A45.x, A45.y, A67.x, A67.y};
        unsigned long long Wj[4] = {W01.x, W01.y, W23.x, W23.y};
        #pragma unroll
        for (int m = 0; m < 8; ++m)
            #pragma unroll
            for (int j = 0; j < 4; ++j)
                FMA2(acc[m * 4 + j], Am[m], Wj[j]);
    }

    // Epilogue: lo half = GEMM1, hi half = GEMM2 ----------------------------
    float bb1[4], bb2[4];
    #pragma unroll
    for (int j = 0; j < 4; ++j) {
        bb1[j] = __ldg(b1 + layer * 64 + j0 + j);
        bb2[j] = __ldg(b2 + layer * 64 + j0 + j);
    }
    float* normL = g_norm + (size_t)layer * N_NODES * EMB;

    #pragma unroll
    for (int m = 0; m < 8; ++m) {
        float o[4];
        #pragma unroll
        for (int j = 0; j < 4; ++j) {
            unsigned long long v = acc[m * 4 + j];
            o[j] = lrelu(lo2(v) + bb1[j]) + lrelu(hi2(v) + bb2[j]);
        }
        float ss = o[0]*o[0] + o[1]*o[1] + o[2]*o[2] + o[3]*o[3];
        #pragma unroll
        for (int off = 8; off; off >>= 1)
            ss += __shfl_xor_sync(0xffffffffu, ss, off);
        float inv = __fdividef(1.0f, fmaxf(sqrtf(ss), 1e-12f));

        int node = base + m0 + m;
        if (node < N_NODES) {
            float4 ov = make_float4(o[0], o[1], o[2], o[3]);
            ((float4*)g_feat)[node * 16 + tx] = ov;
            float4 on = make_float4(o[0]*inv, o[1]*inv, o[2]*inv, o[3]*inv);
            ((float4*)normL)[node * 16 + tx] = on;
        }
    }
}

// ---------------------------------------------------------------------------
// Final gather; also re-zeroes g_cnt to maintain the entry invariant.
__global__ __launch_bounds__(256) void gather_kernel(const int* __restrict__ user,
                                                     const int* __restrict__ pos,
                                                     const int* __restrict__ neg,
                                                     const float* __restrict__ emb,
                                                     float* __restrict__ out) {
    int o4 = blockIdx.x * 256 + threadIdx.x;
    if (o4 < N_NODES) g_cnt[o4] = 0;               // restore invariant
    if (o4 >= 3 * BATCH * 64) return;
    int c4 = o4 & 63;
    int rr = o4 >> 6;
    int tsel = rr / BATCH;
    int r    = rr - tsel * BATCH;
    int node = (tsel == 0) ? user[r]
             : (tsel == 1) ? (N_USERS + pos[r])
                           : (N_USERS + neg[r]);
    int part = c4 >> 4;
    int cc   = c4 & 15;
    float4 v;
    if (part == 0)
        v = ((const float4*)emb)[node * 16 + cc];
    else
        v = ((const float4*)(g_norm + (size_t)(part - 1) * N_NODES * EMB))[node * 16 + cc];
    ((float4*)out)[o4] = v;
}

// ---------------------------------------------------------------------------
extern "C" void kernel_launch(void* const* d_in, const int* in_sizes, int n_in,
                              void* d_out, int out_size) {
    const int*   user = (const int*)  d_in[0];
    const int*   pos  = (const int*)  d_in[1];
    const int*   neg  = (const int*)  d_in[2];
    const int*   row  = (const int*)  d_in[3];
    const int*   col  = (const int*)  d_in[4];
    const float* vals = (const float*)d_in[5];
    const float* emb  = (const float*)d_in[6];
    const float* W1   = (const float*)d_in[7];
    const float* b1   = (const float*)d_in[8];
    const float* W2   = (const float*)d_in[9];
    const float* b2   = (const float*)d_in[10];
    float* out = (float*)d_out;

    static bool attr_set = false;
    if (!attr_set) {
        cudaFuncSetAttribute(dense_kernel,
                             cudaFuncAttributeMaxDynamicSharedMemorySize, DENSE_SMEM);
        attr_set = true;
    }

    const int VEC_BLOCKS   = (N_NODES * EMB / 4 + 255) / 256;   // 7813 (>= NNZ/256)
    const int EDGE_BLOCKS  = (NNZ + 255) / 256;                 // 4883
    const int ROW16_BLOCKS = (N_NODES * 16 + 255) / 256;        // 7813
    const int DENSE_BLOCKS = (N_NODES + M_TILE - 1) / M_TILE;   // 977

    copy_hist_kernel<<<VEC_BLOCKS, 256>>>(emb, row);
    scan1_kernel<<<SCAN_BLOCKS, 256>>>();
    scan2_kernel<<<1, 512>>>();
    scan3_kernel<<<SCAN_BLOCKS, 256>>>();
    scatter_kernel<<<EDGE_BLOCKS, 256>>>(row, col, vals);

    for (int l = 0; l < N_LAYERS; ++l) {
        spmm_csr_kernel<<<ROW16_BLOCKS, 256>>>();
        dense_kernel<<<DENSE_BLOCKS, 256, DENSE_SMEM>>>(W1, b1, W2, b2, l);
    }
    gather_kernel<<<(3 * BATCH * 64 + 255) / 256, 256>>>(user, pos, neg, emb, out);
}